// round 4
// baseline (speedup 1.0000x reference)
#include <cuda_runtime.h>

// ---------------------------------------------------------------------------
// Fused BasicBlockA (see R0-R3 notes). 42 live taps per pixel/stage; only
// ky in {0,1} rows are live. Per pixel per stage there are only 15 unique
// source values (3 ch x {(0,0),(0,1),(0,2),(1,0),(1,1)}): load them ONCE
// into registers, then 42 FMAs. (R3 showed the compiler did not CSE them.)
// ---------------------------------------------------------------------------

#define L_DIM 16
#define WSLOT 44
#define TX 32
#define TY 8
#define XS_H 10
#define XS_W 36
#define HS_H 9
#define HS_W 34
#define HS_N (HS_H * HS_W)   // 306

__device__ float g_wc[2 * L_DIM * WSLOT];

__device__ __forceinline__ float softplus_f(float v) {
    return fmaxf(v, 0.f) + log1pf(expf(-fabsf(v)));
}

// Tap offsets within the 42-tap compact layout, per (i=out ch, j=in ch).
// Taps per (i,j): 4 always [s00,s01,s02,s10] + 1 [s11] iff j<=i.
__device__ __forceinline__ constexpr int woff(int i, int j) {
    constexpr int tbl[9] = {0, 5, 9, 13, 18, 23, 27, 32, 37};
    return tbl[i * 3 + j];
}

__global__ void prep_kernel(const float* __restrict__ w1, const float* __restrict__ c1,
                            const float* __restrict__ w2, const float* __restrict__ c2) {
    int t = threadIdx.x;
    if (t >= 2 * L_DIM) return;
    int stage = t >> 4;
    int l = t & 15;
    const float* W = stage ? w2 : w1;
    const float* C = stage ? c2 : c1;
    float* dst = g_wc + t * WSLOT;
    int s = 0;
    for (int i = 0; i < 3; i++) {
        for (int j = 0; j < 3; j++) {
            int base = ((l * 3 + i) * 3 + j) * 9;
            for (int kx = 0; kx < 3; kx++) dst[s++] = W[base + kx];   // ky=0
            dst[s++] = W[base + 3];                                   // ky=1,kx=0
            if (j <= i) dst[s++] = (j == i) ? softplus_f(C[base + 4]) : W[base + 4];
        }
    }
    dst[42] = 0.f;
    dst[43] = 0.f;
}

// 42 FMAs from 15 register-resident sources s[j][0..4].
__device__ __forceinline__ void conv42(const float (&w)[WSLOT], float a[3],
                                       const float (&s)[3][5]) {
#pragma unroll
    for (int j = 0; j < 3; j++) {
#pragma unroll
        for (int i = 0; i < 3; i++) {
            const int o = woff(i, j);
            a[i] = fmaf(w[o + 0], s[j][0], a[i]);
            a[i] = fmaf(w[o + 1], s[j][1], a[i]);
            a[i] = fmaf(w[o + 2], s[j][2], a[i]);
            a[i] = fmaf(w[o + 3], s[j][3], a[i]);
            if (j <= i) a[i] = fmaf(w[o + 4], s[j][4], a[i]);
        }
    }
}

__global__ __launch_bounds__(256)
void fused_kernel(const float* __restrict__ x, const float* __restrict__ bias1,
                  const float* __restrict__ res, float* __restrict__ out) {
    __shared__ float xs[3][XS_H][XS_W];
    __shared__ float hs[3][HS_H][HS_W];
    __shared__ alignas(16) float sw[2 * L_DIM * WSLOT];
    __shared__ float sb[L_DIM * 3];

    const int tid = threadIdx.x;
    const int b   = blockIdx.z;
    const int gy0 = blockIdx.y * TY;
    const int gx0 = blockIdx.x * TX;

    for (int q = tid; q < 2 * L_DIM * WSLOT; q += 256) sw[q] = g_wc[q];
    if (tid < L_DIM * 3) sb[tid] = bias1[tid];

    const float* xb = x + (size_t)b * 3 * 128 * 128;
    for (int q = tid; q < 3 * XS_H * XS_W; q += 256) {
        int c  = q / (XS_H * XS_W);
        int r  = (q / XS_W) % XS_H;
        int cc = q % XS_W;
        int gy = gy0 - 2 + r;
        int gx = gx0 - 2 + cc;
        float v = 0.f;
        if ((unsigned)gy < 128u && (unsigned)gx < 128u)
            v = xb[(c * 128 + gy) * 128 + gx];
        xs[c][r][cc] = v;
    }
    __syncthreads();

    const int tx = tid & 31;
    const int ty = tid >> 5;

    // Hoisted stage-1 pixel coordinates / border predicates (latent-invariant).
    // Pixel 0: p = tid (always < 306 for tid<256). Pixel 1: p = tid+256.
    const int yy0 = tid / HS_W, xx0 = tid % HS_W;
    const bool in0 = ((unsigned)(gy0 - 1 + yy0) < 128u) && ((unsigned)(gx0 - 1 + xx0) < 128u);
    const int p1 = tid + 256;
    const bool has1 = (p1 < HS_N);
    const int yy1 = has1 ? p1 / HS_W : 0, xx1 = has1 ? p1 % HS_W : 0;
    const bool in1 = has1 && ((unsigned)(gy0 - 1 + yy1) < 128u) && ((unsigned)(gx0 - 1 + xx1) < 128u);

    float acc[3] = {0.f, 0.f, 0.f};

    for (int l = 0; l < L_DIM; l++) {
        alignas(16) float w[WSLOT];
        {
            const float4* p = (const float4*)(sw + l * WSLOT);
#pragma unroll
            for (int q = 0; q < WSLOT / 4; q++) ((float4*)w)[q] = p[q];
        }
        const float b0 = sb[l * 3 + 0], b1 = sb[l * 3 + 1], b2 = sb[l * 3 + 2];

        // ---- stage 1: pixel 0 ----
        {
            float s[3][5];
#pragma unroll
            for (int j = 0; j < 3; j++) {
                s[j][0] = xs[j][yy0][xx0];
                s[j][1] = xs[j][yy0][xx0 + 1];
                s[j][2] = xs[j][yy0][xx0 + 2];
                s[j][3] = xs[j][yy0 + 1][xx0];
                s[j][4] = xs[j][yy0 + 1][xx0 + 1];
            }
            float a[3] = {b0, b1, b2};
            conv42(w, a, s);
#pragma unroll
            for (int i = 0; i < 3; i++) {
                float v = a[i];
                v = (v > 0.f) ? v : (__expf(v) - 1.f);
                hs[i][yy0][xx0] = in0 ? v : 0.f;
            }
        }
        // ---- stage 1: pixel 1 (only 50 threads) ----
        if (has1) {
            float s[3][5];
#pragma unroll
            for (int j = 0; j < 3; j++) {
                s[j][0] = xs[j][yy1][xx1];
                s[j][1] = xs[j][yy1][xx1 + 1];
                s[j][2] = xs[j][yy1][xx1 + 2];
                s[j][3] = xs[j][yy1 + 1][xx1];
                s[j][4] = xs[j][yy1 + 1][xx1 + 1];
            }
            float a[3] = {b0, b1, b2};
            conv42(w, a, s);
#pragma unroll
            for (int i = 0; i < 3; i++) {
                float v = a[i];
                v = (v > 0.f) ? v : (__expf(v) - 1.f);
                hs[i][yy1][xx1] = in1 ? v : 0.f;
            }
        }
        __syncthreads();

        // ---- stage 2 ----
        {
            const float4* p = (const float4*)(sw + (L_DIM + l) * WSLOT);
#pragma unroll
            for (int q = 0; q < WSLOT / 4; q++) ((float4*)w)[q] = p[q];
        }
        {
            float s[3][5];
#pragma unroll
            for (int j = 0; j < 3; j++) {
                s[j][0] = hs[j][ty][tx];
                s[j][1] = hs[j][ty][tx + 1];
                s[j][2] = hs[j][ty][tx + 2];
                s[j][3] = hs[j][ty + 1][tx];
                s[j][4] = hs[j][ty + 1][tx + 1];
            }
            float a[3] = {0.f, 0.f, 0.f};
            conv42(w, a, s);
            acc[0] += a[0];
            acc[1] += a[1];
            acc[2] += a[2];
        }
        __syncthreads();
    }

    const float r = res[0];
    const float g = (r > 0.f) ? r : 0.f;
    const int gy = gy0 + ty, gx = gx0 + tx;
    float* ob = out + (size_t)b * 3 * 128 * 128;
#pragma unroll
    for (int i = 0; i < 3; i++) {
        ob[(i * 128 + gy) * 128 + gx] =
            acc[i] * (1.f / 16.f) + g * xs[i][ty + 2][tx + 2];
    }
}

extern "C" void kernel_launch(void* const* d_in, const int* in_sizes, int n_in,
                              void* d_out, int out_size) {
    const float* x  = (const float*)d_in[0];
    const float* w1 = (const float*)d_in[1];
    const float* c1 = (const float*)d_in[2];
    const float* b1 = (const float*)d_in[3];
    const float* w2 = (const float*)d_in[4];
    const float* c2 = (const float*)d_in[5];
    const float* rs = (const float*)d_in[6];
    (void)in_sizes; (void)n_in; (void)out_size;

    prep_kernel<<<1, 32>>>(w1, c1, w2, c2);

    dim3 grid(128 / TX, 128 / TY, 64);
    fused_kernel<<<grid, 256>>>(x, b1, rs, (float*)d_out);
}